// round 12
// baseline (speedup 1.0000x reference)
#include <cuda_runtime.h>

typedef unsigned long long u64;

// ---- f32x2 packed helpers (sm_103a) ----------------------------------------
__device__ __forceinline__ u64 pk2(float lo, float hi) {
    u64 r; asm("mov.b64 %0, {%1,%2};" : "=l"(r) : "f"(lo), "f"(hi)); return r;
}
__device__ __forceinline__ void up2(u64 v, float& lo, float& hi) {
    asm("mov.b64 {%0,%1}, %2;" : "=f"(lo), "=f"(hi) : "l"(v));
}
__device__ __forceinline__ u64 addx2(u64 a, u64 b) {
    u64 r; asm("add.rn.f32x2 %0, %1, %2;" : "=l"(r) : "l"(a), "l"(b)); return r;
}
__device__ __forceinline__ u64 mulx2(u64 a, u64 b) {
    u64 r; asm("mul.rn.f32x2 %0, %1, %2;" : "=l"(r) : "l"(a), "l"(b)); return r;
}
__device__ __forceinline__ u64 fmax2p(u64 a, u64 b, u64 c) {
    u64 r; asm("fma.rn.f32x2 %0, %1, %2, %3;" : "=l"(r) : "l"(a), "l"(b), "l"(c)); return r;
}

// ---- scratch (device globals; no allocs allowed) ---------------------------
__device__ float g_A2[1024 * 256];     // a' = x@Wg[:D] + bg
__device__ float g_B2[1024 * 256];     // b  = x@Wg[D:]
__device__ float g_paccv[512 * 256];   // per (b*128 + ib*2 + jh): sum rs*v_h
__device__ float g_psrm[512];          // per (b*128 + ib*2 + jh): sum rs*m
__device__ float g_ypart[64 * 256];    // matvec partials per (b, d-slice)

// ---------------------------------------------------------------------------
// Kernel A: a' = x @ Wg[:256] + bg ; b = x @ Wg[256:]
// grid (64, 2), block 256. 16 rows per block; inner loop 4 LDS.128 per d.
// ---------------------------------------------------------------------------
__global__ __launch_bounds__(256) void gemm_ab(const float* __restrict__ x,
                                               const float* __restrict__ Wg,
                                               const float* __restrict__ bg) {
    int z = blockIdx.y;
    int m0 = blockIdx.x * 16;
    const float* __restrict__ W = Wg + z * 65536;   // Wg[(z*256+d)*256 + h]
    __shared__ float xst[256][20];                  // 80B rows: 16B-aligned
    int tid = threadIdx.x;
#pragma unroll
    for (int r = 0; r < 16; r++) xst[tid][r] = x[(m0 + r) * 256 + tid];
    __syncthreads();

    float bias = (z == 0) ? bg[tid] : 0.0f;
    u64 accp[8];
#pragma unroll
    for (int k = 0; k < 8; k++) accp[k] = pk2(bias, bias);

#pragma unroll 16
    for (int d = 0; d < 256; d++) {
        float w = W[d * 256 + tid];
        u64 wp = pk2(w, w);
        const ulonglong2* xr = reinterpret_cast<const ulonglong2*>(&xst[d][0]);
#pragma unroll
        for (int k = 0; k < 4; k++) {
            ulonglong2 t = xr[k];                   // LDS.128 broadcast
            accp[2 * k]     = fmax2p(t.x, wp, accp[2 * k]);
            accp[2 * k + 1] = fmax2p(t.y, wp, accp[2 * k + 1]);
        }
    }

    float* __restrict__ out = z ? g_B2 : g_A2;
#pragma unroll
    for (int k = 0; k < 8; k++) {
        float o0, o1;
        up2(accp[k], o0, o1);
        out[(m0 + 2 * k) * 256 + tid] = o0;
        out[(m0 + 2 * k + 1) * 256 + tid] = o1;
    }
}

// ---------------------------------------------------------------------------
// Kernel B: pair loop. grid (64 ib, 4 b, 2 jh), block 256 (8 warps).
// Warp = 2 groups of 16 lanes; group g handles j = j0 + duo*2 + g. Lane s
// owns 16 h at float4 chunks s + c*16. A tile in smem (broadcast LDS).
// launch_bounds(256,2): cap 128 regs -> guarantee 2 blocks/SM.
// ---------------------------------------------------------------------------
__global__ __launch_bounds__(256, 2) void pair_kernel() {
    int ib = blockIdx.x;
    int b  = blockIdx.y;
    int jh = blockIdx.z;
    int warp = threadIdx.x >> 5;
    int lane = threadIdx.x & 31;
    int g = lane >> 4;     // group -> j parity
    int s = lane & 15;     // sublane -> h chunks

    __shared__ float sa[4][256];   // 4 A rows for this i-tile
    reinterpret_cast<float4*>(&sa[0][0])[threadIdx.x] =
        reinterpret_cast<const float4*>(g_A2 + (b * 256 + ib * 4) * 256)[threadIdx.x];
    __syncthreads();

    const ulonglong2* __restrict__ Bb =
        reinterpret_cast<const ulonglong2*>(g_B2 + b * 65536);

    u64 acc[8];
#pragma unroll
    for (int k = 0; k < 8; k++) acc[k] = 0ull;
    float srm = 0.0f;

    int j0 = jh * 128 + warp * 16;
#pragma unroll 2
    for (int duo = 0; duo < 8; duo++) {
        int j = j0 + duo * 2 + g;
        const ulonglong2* __restrict__ Br = Bb + j * 64 + s;
        u64 bp[8];
#pragma unroll
        for (int c = 0; c < 4; c++) {
            ulonglong2 t = Br[c * 16];
            bp[2 * c] = t.x; bp[2 * c + 1] = t.y;
        }

#pragma unroll
        for (int ii = 0; ii < 4; ii++) {
            const ulonglong2* Ar =
                reinterpret_cast<const ulonglong2*>(&sa[ii][0]) + s;
            u64 vp[8];
#pragma unroll
            for (int c = 0; c < 4; c++) {
                ulonglong2 t = Ar[c * 16];
                vp[2 * c]     = addx2(t.x, bp[2 * c]);
                vp[2 * c + 1] = addx2(t.y, bp[2 * c + 1]);
            }
#pragma unroll
            for (int k = 0; k < 8; k++) {
                float lo, hi; up2(vp[k], lo, hi);
                vp[k] = pk2(fmaxf(lo, 0.0f), fmaxf(hi, 0.0f));
            }
            u64 q0 = mulx2(vp[0], vp[0]);
            u64 q1 = mulx2(vp[1], vp[1]);
            q0 = fmax2p(vp[2], vp[2], q0);
            q1 = fmax2p(vp[3], vp[3], q1);
            q0 = fmax2p(vp[4], vp[4], q0);
            q1 = fmax2p(vp[5], vp[5], q1);
            q0 = fmax2p(vp[6], vp[6], q0);
            q1 = fmax2p(vp[7], vp[7], q1);
            u64 s2p = addx2(q0, q1);
            u64 t0 = addx2(vp[0], vp[1]), t1 = addx2(vp[2], vp[3]);
            u64 t2 = addx2(vp[4], vp[5]), t3 = addx2(vp[6], vp[7]);
            u64 s1p = addx2(addx2(t0, t1), addx2(t2, t3));

            float s1a, s1b; up2(s1p, s1a, s1b);
            float s2a, s2b; up2(s2p, s2a, s2b);
            u64 sv = pk2(s1a + s1b, s2a + s2b);
            sv = addx2(sv, __shfl_xor_sync(0xffffffffu, sv, 1));
            sv = addx2(sv, __shfl_xor_sync(0xffffffffu, sv, 2));
            sv = addx2(sv, __shfl_xor_sync(0xffffffffu, sv, 4));
            sv = addx2(sv, __shfl_xor_sync(0xffffffffu, sv, 8));
            float S1, S2; up2(sv, S1, S2);

            float m   = S1 * (1.0f / 256.0f);
            float var = fmaf(S2, 1.0f / 256.0f, -m * m);
            float rs  = rsqrtf(var + 1e-5f);
            u64 rsp = pk2(rs, rs);
#pragma unroll
            for (int k = 0; k < 8; k++) acc[k] = fmax2p(vp[k], rsp, acc[k]);
            srm = fmaf(rs, m, srm);
        }
    }

#pragma unroll
    for (int k = 0; k < 8; k++)
        acc[k] = addx2(acc[k], __shfl_xor_sync(0xffffffffu, acc[k], 16));
#pragma unroll
    for (int off = 16; off > 0; off >>= 1)
        srm += __shfl_xor_sync(0xffffffffu, srm, off);

    __shared__ float sacc[8][256];
    __shared__ float ssrm[8];
    if (lane < 16) {
        float4* dst = reinterpret_cast<float4*>(&sacc[warp][0]);
#pragma unroll
        for (int c = 0; c < 4; c++) {
            float a0, a1, a2, a3;
            up2(acc[2 * c], a0, a1);
            up2(acc[2 * c + 1], a2, a3);
            dst[s + c * 16] = make_float4(a0, a1, a2, a3);  // h = (s+c*16)*4
        }
        if (lane == 0) ssrm[warp] = srm * 0.0625f;
    }
    __syncthreads();

    int tid = threadIdx.x;
    float tot = 0.0f;
#pragma unroll
    for (int w = 0; w < 8; w++) tot += sacc[w][tid];
    int p = b * 128 + ib * 2 + jh;
    g_paccv[p * 256 + tid] = tot;
    if (tid == 0) {
        float sm = 0.0f;
#pragma unroll
        for (int w = 0; w < 8; w++) sm += ssrm[w];
        g_psrm[p] = sm;
    }
}

// ---------------------------------------------------------------------------
// Kernel C1: matvec partials. grid (16 slices, 4 b), block 256.
// ---------------------------------------------------------------------------
__global__ __launch_bounds__(256) void matvec(const float* __restrict__ Wf,
                                              const float* __restrict__ g_gamma,
                                              const float* __restrict__ g_beta) {
    int r = blockIdx.x;
    int b = blockIdx.y;
    int t = threadIdx.x;

    const float* __restrict__ Wr = Wf + (r * 16) * 256 + t;
    float w[16];
#pragma unroll
    for (int k = 0; k < 16; k++) w[k] = Wr[k * 256];

    int dl = t >> 4;
    int d  = r * 16 + dl;
    int q0 = (t & 15) * 8;
    float part = 0.0f;
#pragma unroll
    for (int q = 0; q < 8; q++)
        part += g_paccv[(b * 128 + q0 + q) * 256 + d];

    __shared__ float sred[16][17];
    __shared__ float ssm[128];
    __shared__ float smtot;
    __shared__ float rs[16];
    sred[dl][t & 15] = part;
    if (t < 128) ssm[t] = g_psrm[b * 128 + t];
    __syncthreads();

    if (t < 32) {
        float sm = ssm[t] + ssm[t + 32] + ssm[t + 64] + ssm[t + 96];
#pragma unroll
        for (int off = 16; off > 0; off >>= 1)
            sm += __shfl_xor_sync(0xffffffffu, sm, off);
        if (t == 0) smtot = sm;
    }
    __syncthreads();
    if (t < 16) {
        float s = 0.0f;
#pragma unroll
        for (int c = 0; c < 16; c++) s += sred[t][c];
        int dd = r * 16 + t;
        rs[t] = g_gamma[dd] * (s - smtot) + 65536.0f * g_beta[dd];
    }
    __syncthreads();

    float y = 0.0f;
#pragma unroll
    for (int k = 0; k < 16; k++) y = fmaf(rs[k], w[k], y);
    g_ypart[(b * 16 + r) * 256 + t] = y;
}

// ---------------------------------------------------------------------------
// Kernel D: fused ln_final + add_out. grid 256, block 256.
// ---------------------------------------------------------------------------
__global__ __launch_bounds__(256) void add_out_ln(const float* __restrict__ x,
                                                  const float* __restrict__ bfv,
                                                  const float* __restrict__ f_gamma,
                                                  const float* __restrict__ f_beta,
                                                  float* __restrict__ out) {
    int blk = blockIdx.x;
    int b = blk >> 6;                // 64 blocks per batch
    int h = threadIdx.x;

    float y = bfv[h];
#pragma unroll
    for (int r = 0; r < 16; r++) y += g_ypart[(b * 16 + r) * 256 + h];
    y = fmaxf(y, 0.0f);

    float s1 = y, s2 = y * y;
#pragma unroll
    for (int off = 16; off > 0; off >>= 1) {
        s1 += __shfl_xor_sync(0xffffffffu, s1, off);
        s2 += __shfl_xor_sync(0xffffffffu, s2, off);
    }
    __shared__ float w1[8], w2[8];
    __shared__ float srel[256];
    int warp = h >> 5, lane = h & 31;
    if (lane == 0) { w1[warp] = s1; w2[warp] = s2; }
    __syncthreads();
    float S1 = 0.0f, S2 = 0.0f;
#pragma unroll
    for (int w = 0; w < 8; w++) { S1 += w1[w]; S2 += w2[w]; }
    float m = S1 * (1.0f / 256.0f);
    float var = fmaf(S2, 1.0f / 256.0f, -m * m);
    float rsq = rsqrtf(var + 1e-5f);
    srel[h] = (y - m) * rsq * f_gamma[h] + f_beta[h];
    __syncthreads();

    int i4 = blk * 256 + h;
    int d  = (h * 4) & 255;
    float4 xv = reinterpret_cast<const float4*>(x)[i4];
    float4 rv = *reinterpret_cast<const float4*>(&srel[d]);
    float4 o;
    o.x = xv.x + rv.x;
    o.y = xv.y + rv.y;
    o.z = xv.z + rv.z;
    o.w = xv.w + rv.w;
    reinterpret_cast<float4*>(out)[i4] = o;
}

// ---------------------------------------------------------------------------
extern "C" void kernel_launch(void* const* d_in, const int* in_sizes, int n_in,
                              void* d_out, int out_size) {
    const float* x       = (const float*)d_in[0];
    const float* Wg      = (const float*)d_in[1];
    const float* bg      = (const float*)d_in[2];
    const float* g_gamma = (const float*)d_in[3];
    const float* g_beta  = (const float*)d_in[4];
    const float* Wf      = (const float*)d_in[5];
    const float* bf      = (const float*)d_in[6];
    const float* f_gamma = (const float*)d_in[7];
    const float* f_beta  = (const float*)d_in[8];
    float* out = (float*)d_out;

    gemm_ab<<<dim3(64, 2), 256>>>(x, Wg, bg);
    pair_kernel<<<dim3(64, 4, 2), 256>>>();
    matvec<<<dim3(16, 4), 256>>>(Wf, g_gamma, g_beta);
    add_out_ln<<<256, 256>>>(x, bf, f_gamma, f_beta, out);
}

// round 13
// speedup vs baseline: 1.0063x; 1.0063x over previous
#include <cuda_runtime.h>

typedef unsigned long long u64;

// ---- f32x2 packed helpers (sm_103a) ----------------------------------------
__device__ __forceinline__ u64 pk2(float lo, float hi) {
    u64 r; asm("mov.b64 %0, {%1,%2};" : "=l"(r) : "f"(lo), "f"(hi)); return r;
}
__device__ __forceinline__ void up2(u64 v, float& lo, float& hi) {
    asm("mov.b64 {%0,%1}, %2;" : "=f"(lo), "=f"(hi) : "l"(v));
}
__device__ __forceinline__ u64 addx2(u64 a, u64 b) {
    u64 r; asm("add.rn.f32x2 %0, %1, %2;" : "=l"(r) : "l"(a), "l"(b)); return r;
}
__device__ __forceinline__ u64 mulx2(u64 a, u64 b) {
    u64 r; asm("mul.rn.f32x2 %0, %1, %2;" : "=l"(r) : "l"(a), "l"(b)); return r;
}
__device__ __forceinline__ u64 fmax2p(u64 a, u64 b, u64 c) {
    u64 r; asm("fma.rn.f32x2 %0, %1, %2, %3;" : "=l"(r) : "l"(a), "l"(b), "l"(c)); return r;
}

// ---- PDL primitives ---------------------------------------------------------
__device__ __forceinline__ void pdl_trigger() {
    asm volatile("griddepcontrol.launch_dependents;" ::: "memory");
}
__device__ __forceinline__ void pdl_wait() {
    asm volatile("griddepcontrol.wait;" ::: "memory");
}

// ---- scratch (device globals; no allocs allowed) ---------------------------
__device__ float g_A2[1024 * 256];     // a' = x@Wg[:D] + bg
__device__ float g_B2[1024 * 256];     // b  = x@Wg[D:]
__device__ float g_paccv[512 * 256];   // per (b*128 + ib*2 + jh): sum rs*v_h
__device__ float g_psrm[512];          // per (b*128 + ib*2 + jh): sum rs*m
__device__ float g_ypart[64 * 256];    // matvec partials per (b, d-slice)

// ---------------------------------------------------------------------------
// Kernel A: a' = x @ Wg[:256] + bg ; b = x @ Wg[256:]
// grid (64, 2), block 256. 16 rows per block; inner loop 4 LDS.128 per d.
// ---------------------------------------------------------------------------
__global__ __launch_bounds__(256) void gemm_ab(const float* __restrict__ x,
                                               const float* __restrict__ Wg,
                                               const float* __restrict__ bg) {
    pdl_trigger();                                  // let pair_kernel launch
    int z = blockIdx.y;
    int m0 = blockIdx.x * 16;
    const float* __restrict__ W = Wg + z * 65536;   // Wg[(z*256+d)*256 + h]
    __shared__ float xst[256][20];                  // 80B rows: 16B-aligned
    int tid = threadIdx.x;
#pragma unroll
    for (int r = 0; r < 16; r++) xst[tid][r] = x[(m0 + r) * 256 + tid];
    __syncthreads();

    float bias = (z == 0) ? bg[tid] : 0.0f;
    u64 accp[8];
#pragma unroll
    for (int k = 0; k < 8; k++) accp[k] = pk2(bias, bias);

#pragma unroll 16
    for (int d = 0; d < 256; d++) {
        float w = W[d * 256 + tid];
        u64 wp = pk2(w, w);
        const ulonglong2* xr = reinterpret_cast<const ulonglong2*>(&xst[d][0]);
#pragma unroll
        for (int k = 0; k < 4; k++) {
            ulonglong2 t = xr[k];                   // LDS.128 broadcast
            accp[2 * k]     = fmax2p(t.x, wp, accp[2 * k]);
            accp[2 * k + 1] = fmax2p(t.y, wp, accp[2 * k + 1]);
        }
    }

    float* __restrict__ out = z ? g_B2 : g_A2;
#pragma unroll
    for (int k = 0; k < 8; k++) {
        float o0, o1;
        up2(accp[k], o0, o1);
        out[(m0 + 2 * k) * 256 + tid] = o0;
        out[(m0 + 2 * k + 1) * 256 + tid] = o1;
    }
}

// ---------------------------------------------------------------------------
// Kernel B: pair loop. grid (64 ib, 4 b, 2 jh), block 256 (8 warps).
// Warp = 2 groups of 16 lanes; group g handles j = j0 + duo*2 + g. Lane s
// owns 16 h at float4 chunks s + c*16. A tile in smem (broadcast LDS).
// ---------------------------------------------------------------------------
__global__ __launch_bounds__(256) void pair_kernel() {
    pdl_trigger();                                  // let matvec launch
    int ib = blockIdx.x;
    int b  = blockIdx.y;
    int jh = blockIdx.z;
    int warp = threadIdx.x >> 5;
    int lane = threadIdx.x & 31;
    int g = lane >> 4;     // group -> j parity
    int s = lane & 15;     // sublane -> h chunks

    pdl_wait();                                     // gemm output now valid

    __shared__ float sa[4][256];   // 4 A rows for this i-tile
    reinterpret_cast<float4*>(&sa[0][0])[threadIdx.x] =
        reinterpret_cast<const float4*>(g_A2 + (b * 256 + ib * 4) * 256)[threadIdx.x];
    __syncthreads();

    const ulonglong2* __restrict__ Bb =
        reinterpret_cast<const ulonglong2*>(g_B2 + b * 65536);

    u64 acc[8];
#pragma unroll
    for (int k = 0; k < 8; k++) acc[k] = 0ull;
    float srm = 0.0f;

    int j0 = jh * 128 + warp * 16;
#pragma unroll 2
    for (int duo = 0; duo < 8; duo++) {
        int j = j0 + duo * 2 + g;
        const ulonglong2* __restrict__ Br = Bb + j * 64 + s;
        u64 bp[8];
#pragma unroll
        for (int c = 0; c < 4; c++) {
            ulonglong2 t = Br[c * 16];
            bp[2 * c] = t.x; bp[2 * c + 1] = t.y;
        }

#pragma unroll
        for (int ii = 0; ii < 4; ii++) {
            const ulonglong2* Ar =
                reinterpret_cast<const ulonglong2*>(&sa[ii][0]) + s;
            u64 vp[8];
#pragma unroll
            for (int c = 0; c < 4; c++) {
                ulonglong2 t = Ar[c * 16];
                vp[2 * c]     = addx2(t.x, bp[2 * c]);
                vp[2 * c + 1] = addx2(t.y, bp[2 * c + 1]);
            }
#pragma unroll
            for (int k = 0; k < 8; k++) {
                float lo, hi; up2(vp[k], lo, hi);
                vp[k] = pk2(fmaxf(lo, 0.0f), fmaxf(hi, 0.0f));
            }
            u64 q0 = mulx2(vp[0], vp[0]);
            u64 q1 = mulx2(vp[1], vp[1]);
            q0 = fmax2p(vp[2], vp[2], q0);
            q1 = fmax2p(vp[3], vp[3], q1);
            q0 = fmax2p(vp[4], vp[4], q0);
            q1 = fmax2p(vp[5], vp[5], q1);
            q0 = fmax2p(vp[6], vp[6], q0);
            q1 = fmax2p(vp[7], vp[7], q1);
            u64 s2p = addx2(q0, q1);
            u64 t0 = addx2(vp[0], vp[1]), t1 = addx2(vp[2], vp[3]);
            u64 t2 = addx2(vp[4], vp[5]), t3 = addx2(vp[6], vp[7]);
            u64 s1p = addx2(addx2(t0, t1), addx2(t2, t3));

            float s1a, s1b; up2(s1p, s1a, s1b);
            float s2a, s2b; up2(s2p, s2a, s2b);
            u64 sv = pk2(s1a + s1b, s2a + s2b);
            sv = addx2(sv, __shfl_xor_sync(0xffffffffu, sv, 1));
            sv = addx2(sv, __shfl_xor_sync(0xffffffffu, sv, 2));
            sv = addx2(sv, __shfl_xor_sync(0xffffffffu, sv, 4));
            sv = addx2(sv, __shfl_xor_sync(0xffffffffu, sv, 8));
            float S1, S2; up2(sv, S1, S2);

            float m   = S1 * (1.0f / 256.0f);
            float var = fmaf(S2, 1.0f / 256.0f, -m * m);
            float rs  = rsqrtf(var + 1e-5f);
            u64 rsp = pk2(rs, rs);
#pragma unroll
            for (int k = 0; k < 8; k++) acc[k] = fmax2p(vp[k], rsp, acc[k]);
            srm = fmaf(rs, m, srm);
        }
    }

#pragma unroll
    for (int k = 0; k < 8; k++)
        acc[k] = addx2(acc[k], __shfl_xor_sync(0xffffffffu, acc[k], 16));
#pragma unroll
    for (int off = 16; off > 0; off >>= 1)
        srm += __shfl_xor_sync(0xffffffffu, srm, off);

    __shared__ float sacc[8][256];
    __shared__ float ssrm[8];
    if (lane < 16) {
        float4* dst = reinterpret_cast<float4*>(&sacc[warp][0]);
#pragma unroll
        for (int c = 0; c < 4; c++) {
            float a0, a1, a2, a3;
            up2(acc[2 * c], a0, a1);
            up2(acc[2 * c + 1], a2, a3);
            dst[s + c * 16] = make_float4(a0, a1, a2, a3);  // h = (s+c*16)*4
        }
        if (lane == 0) ssrm[warp] = srm * 0.0625f;
    }
    __syncthreads();

    int tid = threadIdx.x;
    float tot = 0.0f;
#pragma unroll
    for (int w = 0; w < 8; w++) tot += sacc[w][tid];
    int p = b * 128 + ib * 2 + jh;
    g_paccv[p * 256 + tid] = tot;
    if (tid == 0) {
        float sm = 0.0f;
#pragma unroll
        for (int w = 0; w < 8; w++) sm += ssrm[w];
        g_psrm[p] = sm;
    }
}

// ---------------------------------------------------------------------------
// Kernel C1: matvec partials. grid (16 slices, 4 b), block 256.
// Wf prefetch happens BEFORE pdl_wait -> overlaps pair_kernel's tail.
// ---------------------------------------------------------------------------
__global__ __launch_bounds__(256) void matvec(const float* __restrict__ Wf,
                                              const float* __restrict__ g_gamma,
                                              const float* __restrict__ g_beta) {
    pdl_trigger();                                  // let add_out_ln launch
    int r = blockIdx.x;
    int b = blockIdx.y;
    int t = threadIdx.x;

    // Prefetch Wf slice (input — independent of pair_kernel output).
    const float* __restrict__ Wr = Wf + (r * 16) * 256 + t;
    float w[16];
#pragma unroll
    for (int k = 0; k < 16; k++) w[k] = Wr[k * 256];

    pdl_wait();                                     // pair output now valid

    int dl = t >> 4;
    int d  = r * 16 + dl;
    int q0 = (t & 15) * 8;
    float part = 0.0f;
#pragma unroll
    for (int q = 0; q < 8; q++)
        part += g_paccv[(b * 128 + q0 + q) * 256 + d];

    __shared__ float sred[16][17];
    __shared__ float ssm[128];
    __shared__ float smtot;
    __shared__ float rs[16];
    sred[dl][t & 15] = part;
    if (t < 128) ssm[t] = g_psrm[b * 128 + t];
    __syncthreads();

    if (t < 32) {
        float sm = ssm[t] + ssm[t + 32] + ssm[t + 64] + ssm[t + 96];
#pragma unroll
        for (int off = 16; off > 0; off >>= 1)
            sm += __shfl_xor_sync(0xffffffffu, sm, off);
        if (t == 0) smtot = sm;
    }
    __syncthreads();
    if (t < 16) {
        float s = 0.0f;
#pragma unroll
        for (int c = 0; c < 16; c++) s += sred[t][c];
        int dd = r * 16 + t;
        rs[t] = g_gamma[dd] * (s - smtot) + 65536.0f * g_beta[dd];
    }
    __syncthreads();

    float y = 0.0f;
#pragma unroll
    for (int k = 0; k < 16; k++) y = fmaf(rs[k], w[k], y);
    g_ypart[(b * 16 + r) * 256 + t] = y;
}

// ---------------------------------------------------------------------------
// Kernel D: fused ln_final + add_out. grid 256, block 256.
// x / bf loads happen BEFORE pdl_wait -> overlap matvec.
// ---------------------------------------------------------------------------
__global__ __launch_bounds__(256) void add_out_ln(const float* __restrict__ x,
                                                  const float* __restrict__ bfv,
                                                  const float* __restrict__ f_gamma,
                                                  const float* __restrict__ f_beta,
                                                  float* __restrict__ out) {
    int blk = blockIdx.x;
    int b = blk >> 6;                // 64 blocks per batch
    int h = threadIdx.x;

    // Prefetch inputs independent of matvec output.
    int i4 = blk * 256 + h;
    float4 xv = reinterpret_cast<const float4*>(x)[i4];
    float y = bfv[h];

    pdl_wait();                                     // g_ypart now valid

#pragma unroll
    for (int r = 0; r < 16; r++) y += g_ypart[(b * 16 + r) * 256 + h];
    y = fmaxf(y, 0.0f);

    float s1 = y, s2 = y * y;
#pragma unroll
    for (int off = 16; off > 0; off >>= 1) {
        s1 += __shfl_xor_sync(0xffffffffu, s1, off);
        s2 += __shfl_xor_sync(0xffffffffu, s2, off);
    }
    __shared__ float w1[8], w2[8];
    __shared__ float srel[256];
    int warp = h >> 5, lane = h & 31;
    if (lane == 0) { w1[warp] = s1; w2[warp] = s2; }
    __syncthreads();
    float S1 = 0.0f, S2 = 0.0f;
#pragma unroll
    for (int w = 0; w < 8; w++) { S1 += w1[w]; S2 += w2[w]; }
    float m = S1 * (1.0f / 256.0f);
    float var = fmaf(S2, 1.0f / 256.0f, -m * m);
    float rsq = rsqrtf(var + 1e-5f);
    srel[h] = (y - m) * rsq * f_gamma[h] + f_beta[h];
    __syncthreads();

    int d  = (h * 4) & 255;
    float4 rv = *reinterpret_cast<const float4*>(&srel[d]);
    float4 o;
    o.x = xv.x + rv.x;
    o.y = xv.y + rv.y;
    o.z = xv.z + rv.z;
    o.w = xv.w + rv.w;
    reinterpret_cast<float4*>(out)[i4] = o;
}

// ---------------------------------------------------------------------------
static inline void launch_pdl(const void* func, dim3 grid, dim3 block,
                              void** args) {
    cudaLaunchConfig_t cfg;
    cfg.gridDim = grid;
    cfg.blockDim = block;
    cfg.dynamicSmemBytes = 0;
    cfg.stream = 0;
    static cudaLaunchAttribute attr[1];
    attr[0].id = cudaLaunchAttributeProgrammaticStreamSerialization;
    attr[0].val.programmaticStreamSerializationAllowed = 1;
    cfg.attrs = attr;
    cfg.numAttrs = 1;
    cudaLaunchKernelExC(&cfg, func, args);
}

extern "C" void kernel_launch(void* const* d_in, const int* in_sizes, int n_in,
                              void* d_out, int out_size) {
    const float* x       = (const float*)d_in[0];
    const float* Wg      = (const float*)d_in[1];
    const float* bg      = (const float*)d_in[2];
    const float* g_gamma = (const float*)d_in[3];
    const float* g_beta  = (const float*)d_in[4];
    const float* Wf      = (const float*)d_in[5];
    const float* bf      = (const float*)d_in[6];
    const float* f_gamma = (const float*)d_in[7];
    const float* f_beta  = (const float*)d_in[8];
    float* out = (float*)d_out;

    void* a1[] = {(void*)&x, (void*)&Wg, (void*)&bg};
    launch_pdl((const void*)gemm_ab, dim3(64, 2), dim3(256), a1);

    launch_pdl((const void*)pair_kernel, dim3(64, 4, 2), dim3(256), nullptr);

    void* a3[] = {(void*)&Wf, (void*)&g_gamma, (void*)&g_beta};
    launch_pdl((const void*)matvec, dim3(16, 4), dim3(256), a3);

    void* a4[] = {(void*)&x, (void*)&bf, (void*)&f_gamma, (void*)&f_beta,
                  (void*)&out};
    launch_pdl((const void*)add_out_ln, dim3(256), dim3(256), a4);
}